// round 2
// baseline (speedup 1.0000x reference)
#include <cuda_runtime.h>

#define N_TOKS 32768
#define EMBED  512
#define NCLS   16
#define NBATCH 8
#define NHEAD  8
#define DHEAD  64
#define RDIM   128            // NHEAD * NCLS
#define SCALE  0.125f         // DHEAD^-0.5

#define TN 64                 // tokens per block
#define QS_STRIDE 65
#define SS_STRIDE 129
#define PS_STRIDE 65

// scratch (device globals — no allocation allowed)
__device__ float g_KP[NBATCH*NCLS*EMBED];
__device__ float g_VP[NBATCH*NCLS*EMBED];
__device__ float g_S [NBATCH*RDIM*EMBED];
__device__ float g_T [NBATCH*RDIM*EMBED];
__device__ float g_C [NBATCH*RDIM];

// ---------------------------------------------------------------------------
// P1: K/V pointwise projections.  KP[b,l,f] = key[l,b,:]·Wk[f,:] + bk[f]
// grid: 256 blocks (128 K + 128 V), 512 threads (one output feature each)
// ---------------------------------------------------------------------------
__global__ void proj_kv_kernel(const float* __restrict__ key,
                               const float* __restrict__ value,
                               const float* __restrict__ Wk, const float* __restrict__ bk,
                               const float* __restrict__ Wv, const float* __restrict__ bv) {
    __shared__ float vecs[EMBED];
    const int x   = blockIdx.x;
    const int isV = x >> 7;
    const int rem = x & 127;
    const int b = rem >> 4, l = rem & 15;
    const int tid = threadIdx.x;

    const float* src = isV ? value : key;
    vecs[tid] = src[(l*NBATCH + b)*EMBED + tid];
    __syncthreads();

    const float* W = isV ? Wv : Wk;
    const float* wrow = W + tid*EMBED;
    float acc = 0.f;
    #pragma unroll 8
    for (int e = 0; e < EMBED; e++) acc += wrow[e] * vecs[e];

    float bias = isV ? bv[tid] : bk[tid];
    float* dst = isV ? g_VP : g_KP;
    dst[(b*NCLS + l)*EMBED + tid] = acc + bias;
}

// ---------------------------------------------------------------------------
// P2: fold projections into per-batch score/output tables.
//   S[b,r,f] = SCALE * sum_d Wq[(h*64+d), f] * KP[b,l,h*64+d]
//   C[b,r]   = SCALE * sum_d bq[h*64+d]      * KP[b,l,h*64+d]
//   T[b,r,e] =         sum_d Wo[e, h*64+d]   * VP[b,l,h*64+d]
// grid: 2048 blocks (1024 S + 1024 T), 512 threads
// ---------------------------------------------------------------------------
__global__ void build_st_kernel(const float* __restrict__ Wq, const float* __restrict__ bq,
                                const float* __restrict__ Wo) {
    __shared__ float vec[DHEAD];
    const int x   = blockIdx.x;
    const int isT = x >> 10;
    const int idx = x & 1023;
    const int b = idx >> 7, r = idx & 127;
    const int h = r >> 4,   l = r & 15;
    const int tid = threadIdx.x;

    const float* src = isT ? g_VP : g_KP;
    if (tid < DHEAD)
        vec[tid] = src[(b*NCLS + l)*EMBED + h*DHEAD + tid];
    __syncthreads();

    float acc = 0.f;
    if (!isT) {
        #pragma unroll 8
        for (int d = 0; d < DHEAD; d++)
            acc += Wq[(h*DHEAD + d)*EMBED + tid] * vec[d];
        g_S[(b*RDIM + r)*EMBED + tid] = acc * SCALE;
        if (tid == 0) {
            float c = 0.f;
            for (int d = 0; d < DHEAD; d++) c += bq[h*DHEAD + d] * vec[d];
            g_C[b*RDIM + r] = c * SCALE;
        }
    } else {
        const float* wrow = Wo + tid*EMBED + h*DHEAD;
        #pragma unroll 8
        for (int d = 0; d < DHEAD; d++)
            acc += wrow[d] * vec[d];
        g_T[(b*RDIM + r)*EMBED + tid] = acc;
    }
}

// ---------------------------------------------------------------------------
// Main: per 64-token tile:
//   scores = Qtile @ S_b^T  (K=512) -> warp-shuffle softmax over 16 classes
//   out    = P @ T_b + bo   (K=128)
// 256 threads, thread (tx,ty) owns tokens {ty+16i} x r/e {tx+16j}
// ---------------------------------------------------------------------------
__global__ __launch_bounds__(256)
void attn_main_kernel(const float* __restrict__ query,
                      const int*   __restrict__ bidx,
                      const float* __restrict__ bo,
                      float*       __restrict__ out) {
    extern __shared__ float sm[];
    float* Qs  = sm;                        // 32 x 65
    float* Ss  = Qs  + 32*QS_STRIDE;        // 32 x 129 (reused as T tile)
    float* Ps  = Ss  + 32*SS_STRIDE;        // 128 x 65
    float* bos = Ps  + RDIM*PS_STRIDE;      // 512
    int*   bt    = (int*)(bos + EMBED);     // 64
    int*   flags = bt + TN;                 // 8

    const int tid = threadIdx.x;
    const int tx  = tid & 15;               // r/e lane
    const int ty  = tid >> 4;               // token lane
    const int n0  = blockIdx.x * TN;

    if (tid < 8) flags[tid] = 0;
    bos[tid]       = bo[tid];
    bos[tid + 256] = bo[tid + 256];
    __syncthreads();
    if (tid < TN) { int b = bidx[n0 + tid]; bt[tid] = b; flags[b] = 1; }
    __syncthreads();

    for (int b = 0; b < NBATCH; b++) {
        if (!flags[b]) continue;
        const float* Sb = g_S + b*RDIM*EMBED;
        const float* Tb = g_T + b*RDIM*EMBED;

        // ---------------- Phase A: scores = Q @ S_b^T ----------------
        float acc[4][8];
        #pragma unroll
        for (int i = 0; i < 4; i++)
            #pragma unroll
            for (int j = 0; j < 8; j++) acc[i][j] = 0.f;

        for (int k0 = 0; k0 < EMBED; k0 += 32) {
            #pragma unroll
            for (int i = 0; i < 8; i++) {          // 64x32 / 256
                int idx = tid + i*256;
                int t = idx >> 5, kc = idx & 31;
                Qs[kc*QS_STRIDE + t] = query[(n0 + t)*EMBED + k0 + kc];
            }
            #pragma unroll
            for (int i = 0; i < 16; i++) {         // 128x32 / 256
                int idx = tid + i*256;
                int r = idx >> 5, kc = idx & 31;
                Ss[kc*SS_STRIDE + r] = Sb[r*EMBED + k0 + kc];
            }
            __syncthreads();
            #pragma unroll 8
            for (int kc = 0; kc < 32; kc++) {
                float qv[4], sv[8];
                #pragma unroll
                for (int i = 0; i < 4; i++) qv[i] = Qs[kc*QS_STRIDE + ty + 16*i];
                #pragma unroll
                for (int j = 0; j < 8; j++) sv[j] = Ss[kc*SS_STRIDE + tx + 16*j];
                #pragma unroll
                for (int i = 0; i < 4; i++)
                    #pragma unroll
                    for (int j = 0; j < 8; j++)
                        acc[i][j] += qv[i] * sv[j];
            }
            __syncthreads();
        }

        // ------- Phase B: softmax over l = tx (16 lanes), h = j -------
        #pragma unroll
        for (int i = 0; i < 4; i++) {
            #pragma unroll
            for (int j = 0; j < 8; j++) {
                float v = acc[i][j] + g_C[b*RDIM + 16*j + tx];
                float m = v;
                m = fmaxf(m, __shfl_xor_sync(0xFFFFFFFFu, m, 8));
                m = fmaxf(m, __shfl_xor_sync(0xFFFFFFFFu, m, 4));
                m = fmaxf(m, __shfl_xor_sync(0xFFFFFFFFu, m, 2));
                m = fmaxf(m, __shfl_xor_sync(0xFFFFFFFFu, m, 1));
                float e = __expf(v - m);
                float s = e;
                s += __shfl_xor_sync(0xFFFFFFFFu, s, 8);
                s += __shfl_xor_sync(0xFFFFFFFFu, s, 4);
                s += __shfl_xor_sync(0xFFFFFFFFu, s, 2);
                s += __shfl_xor_sync(0xFFFFFFFFu, s, 1);
                Ps[(16*j + tx)*PS_STRIDE + ty + 16*i] = e / s;
            }
        }

        // ---------------- Phase C: out = P @ T_b + bo ----------------
        for (int e0 = 0; e0 < EMBED; e0 += 128) {
            float oacc[4][8];
            #pragma unroll
            for (int i = 0; i < 4; i++)
                #pragma unroll
                for (int j = 0; j < 8; j++) oacc[i][j] = 0.f;

            for (int k0 = 0; k0 < RDIM; k0 += 32) {
                __syncthreads();                    // also orders Ps writes before first read
                #pragma unroll
                for (int i = 0; i < 16; i++) {      // 32x128 / 256
                    int idx = tid + i*256;
                    int ec = idx & 127, kcl = idx >> 7;
                    Ss[kcl*SS_STRIDE + ec] = Tb[(k0 + kcl)*EMBED + e0 + ec];
                }
                __syncthreads();
                #pragma unroll 8
                for (int kc = 0; kc < 32; kc++) {
                    float pv[4], tv[8];
                    #pragma unroll
                    for (int i = 0; i < 4; i++) pv[i] = Ps[(k0 + kc)*PS_STRIDE + ty + 16*i];
                    #pragma unroll
                    for (int j = 0; j < 8; j++) tv[j] = Ss[kc*SS_STRIDE + tx + 16*j];
                    #pragma unroll
                    for (int i = 0; i < 4; i++)
                        #pragma unroll
                        for (int j = 0; j < 8; j++)
                            oacc[i][j] += pv[i] * tv[j];
                }
            }
            #pragma unroll
            for (int i = 0; i < 4; i++) {
                int t = ty + 16*i;
                if (bt[t] == b) {
                    #pragma unroll
                    for (int j = 0; j < 8; j++) {
                        int e = e0 + tx + 16*j;
                        out[(n0 + t)*EMBED + e] = oacc[i][j] + bos[e];
                    }
                }
            }
        }
        __syncthreads();
    }
}

// ---------------------------------------------------------------------------
extern "C" void kernel_launch(void* const* d_in, const int* in_sizes, int n_in,
                              void* d_out, int out_size) {
    const float* query = (const float*)d_in[0];
    const float* key   = (const float*)d_in[1];
    const float* value = (const float*)d_in[2];
    const int*   bidx  = (const int*)  d_in[3];
    const int off = (n_in >= 13) ? 5 : 4;   // skip scalar batch_size if present
    const float* Wq = (const float*)d_in[off + 0];
    const float* bq = (const float*)d_in[off + 1];
    const float* Wk = (const float*)d_in[off + 2];
    const float* bk = (const float*)d_in[off + 3];
    const float* Wv = (const float*)d_in[off + 4];
    const float* bv = (const float*)d_in[off + 5];
    const float* Wo = (const float*)d_in[off + 6];
    const float* bo = (const float*)d_in[off + 7];
    float* out = (float*)d_out;

    const int smem_bytes = (32*QS_STRIDE + 32*SS_STRIDE + RDIM*PS_STRIDE + EMBED) * 4
                         + (TN + 8) * 4;
    cudaFuncSetAttribute(attn_main_kernel,
                         cudaFuncAttributeMaxDynamicSharedMemorySize, smem_bytes);

    proj_kv_kernel <<<256, 512>>>(key, value, Wk, bk, Wv, bv);
    build_st_kernel<<<2048, 512>>>(Wq, bq, Wo);
    attn_main_kernel<<<N_TOKS / TN, 256, smem_bytes>>>(query, bidx, bo, out);
}

// round 3
// speedup vs baseline: 1.8358x; 1.8358x over previous
#include <cuda_runtime.h>

#define N_TOKS 32768
#define EMBED  512
#define NCLS   16
#define NBATCH 8
#define NHEAD  8
#define DHEAD  64
#define RDIM   128            // NHEAD * NCLS
#define SCALE  0.125f         // DHEAD^-0.5

#define TN 64                 // tokens per block (main kernel)
#define QS_STRIDE 65
#define SS_STRIDE 129
#define PS_STRIDE 65

// scratch (device globals — no allocation allowed)
__device__ float g_KP[NBATCH*NCLS*EMBED];
__device__ float g_VP[NBATCH*NCLS*EMBED];
__device__ float g_S [NBATCH*RDIM*EMBED];
__device__ float g_T [NBATCH*RDIM*EMBED];
__device__ float g_C [NBATCH*RDIM];

// ---------------------------------------------------------------------------
// P1: K/V pointwise projections as a tiled GEMM.
//   C[r=(b*16+l), f] = X[r,:] · W[f,:] + bias[f],  X row r -> src[(l*8+b)*512]
// Tiles: 64 rows x 64 f, K-chunks of 32. grid = 32 blocks, 256 threads.
// All global loads are contiguous 128B rows.
// ---------------------------------------------------------------------------
__global__ __launch_bounds__(256)
void proj_kv_kernel(const float* __restrict__ key,
                    const float* __restrict__ value,
                    const float* __restrict__ Wk, const float* __restrict__ bk,
                    const float* __restrict__ Wv, const float* __restrict__ bv) {
    __shared__ float Xs[32][65];
    __shared__ float Ws[32][65];

    const int bx  = blockIdx.x;
    const int isV = bx >> 4;
    const int ft  = (bx >> 1) & 7;
    const int rt  = bx & 1;
    const int f0  = ft * 64;
    const int r0  = rt * 64;
    const int tid = threadIdx.x;
    const int tx  = tid & 15;          // f lane
    const int ty  = tid >> 4;          // row lane

    const float* src  = isV ? value : key;
    const float* W    = isV ? Wv : Wk;
    const float* bias = isV ? bv : bk;
    float*       dst  = isV ? g_VP : g_KP;

    float acc[4][4];
    #pragma unroll
    for (int i = 0; i < 4; i++)
        #pragma unroll
        for (int j = 0; j < 4; j++) acc[i][j] = 0.f;

    for (int k0 = 0; k0 < EMBED; k0 += 32) {
        #pragma unroll
        for (int i = 0; i < 8; i++) {              // 64r x 32k
            int idx = tid + i*256;
            int rr = idx >> 5, kc = idx & 31;
            int r = r0 + rr, b = r >> 4, l = r & 15;
            Xs[kc][rr] = src[(l*NBATCH + b)*EMBED + k0 + kc];
        }
        #pragma unroll
        for (int i = 0; i < 8; i++) {              // 64f x 32k
            int idx = tid + i*256;
            int fl = idx >> 5, kc = idx & 31;
            Ws[kc][fl] = W[(f0 + fl)*EMBED + k0 + kc];
        }
        __syncthreads();
        #pragma unroll 8
        for (int kc = 0; kc < 32; kc++) {
            float xv[4], wv[4];
            #pragma unroll
            for (int i = 0; i < 4; i++) xv[i] = Xs[kc][ty + 16*i];
            #pragma unroll
            for (int j = 0; j < 4; j++) wv[j] = Ws[kc][tx + 16*j];
            #pragma unroll
            for (int i = 0; i < 4; i++)
                #pragma unroll
                for (int j = 0; j < 4; j++)
                    acc[i][j] += xv[i] * wv[j];
        }
        __syncthreads();
    }
    #pragma unroll
    for (int i = 0; i < 4; i++)
        #pragma unroll
        for (int j = 0; j < 4; j++) {
            int f = f0 + tx + 16*j;
            dst[(r0 + ty + 16*i)*EMBED + f] = acc[i][j] + bias[f];
        }
}

// ---------------------------------------------------------------------------
// P2: fold Wq into score table S and Wo into output table T (K=64 per head).
//   S[b,(h,l),f] = SCALE * sum_d KP[b,l,h*64+d] * Wq[h*64+d, f]
//   T[b,(h,l),e] =         sum_d VP[b,l,h*64+d] * Wo[e, h*64+d]
//   C[b,(h,l)]   = SCALE * sum_d KP[b,l,h*64+d] * bq[h*64+d]
// One block per (mat, b, h, 128-wide f-chunk): grid = 2*8*8*4 = 512 blocks.
// ---------------------------------------------------------------------------
__global__ __launch_bounds__(256)
void build_st_kernel(const float* __restrict__ Wq, const float* __restrict__ bq,
                     const float* __restrict__ Wo) {
    __shared__ float Ps[16][65];       // KP/VP head slice [l][d]
    __shared__ float Ws[64][129];      // weight slice [d][f]

    const int bx  = blockIdx.x;
    const int isT = bx >> 8;
    const int rem = bx & 255;
    const int b   = rem >> 5;
    const int h   = (rem >> 2) & 7;
    const int f0  = (rem & 3) * 128;
    const int tid = threadIdx.x;
    const int tx  = tid & 31;
    const int ty  = tid >> 5;          // 0..7

    const float* src = isT ? g_VP : g_KP;
    #pragma unroll
    for (int i = 0; i < 4; i++) {      // 16l x 64d
        int idx = tid + i*256;
        int l = idx >> 6, d = idx & 63;
        Ps[l][d] = src[(b*NCLS + l)*EMBED + h*DHEAD + d];
    }
    if (!isT) {
        #pragma unroll
        for (int i = 0; i < 32; i++) { // 64d x 128f
            int idx = tid + i*256;
            int d = idx >> 7, fc = idx & 127;
            Ws[d][fc] = Wq[(h*DHEAD + d)*EMBED + f0 + fc];
        }
    } else {
        #pragma unroll
        for (int i = 0; i < 32; i++) { // 128e x 64d (d fast -> coalesced)
            int idx = tid + i*256;
            int ec = idx >> 6, d = idx & 63;
            Ws[d][ec] = Wo[(f0 + ec)*EMBED + h*DHEAD + d];
        }
    }
    __syncthreads();

    float acc[2][4];
    #pragma unroll
    for (int i = 0; i < 2; i++)
        #pragma unroll
        for (int j = 0; j < 4; j++) acc[i][j] = 0.f;

    #pragma unroll 8
    for (int d = 0; d < DHEAD; d++) {
        float pv[2], wv[4];
        #pragma unroll
        for (int i = 0; i < 2; i++) pv[i] = Ps[ty + 8*i][d];
        #pragma unroll
        for (int j = 0; j < 4; j++) wv[j] = Ws[d][tx + 32*j];
        #pragma unroll
        for (int i = 0; i < 2; i++)
            #pragma unroll
            for (int j = 0; j < 4; j++)
                acc[i][j] += pv[i] * wv[j];
    }

    float* dst = isT ? g_T : g_S;
    const float mul = isT ? 1.f : SCALE;
    #pragma unroll
    for (int i = 0; i < 2; i++) {
        int r = h*NCLS + ty + 8*i;
        #pragma unroll
        for (int j = 0; j < 4; j++)
            dst[(b*RDIM + r)*EMBED + f0 + tx + 32*j] = acc[i][j] * mul;
    }

    if (!isT && f0 == 0 && tid < NCLS) {
        float c = 0.f;
        #pragma unroll 8
        for (int d = 0; d < DHEAD; d++) c += bq[h*DHEAD + d] * Ps[tid][d];
        g_C[b*RDIM + h*NCLS + tid] = c * SCALE;
    }
}

// ---------------------------------------------------------------------------
// Main: per 64-token tile:
//   scores = Qtile @ S_b^T  (K=512) -> warp-shuffle softmax over 16 classes
//   out    = P @ T_b + bo   (K=128)
// 256 threads, thread (tx,ty) owns tokens {ty+16i} x r/e {tx+16j}
// ---------------------------------------------------------------------------
__global__ __launch_bounds__(256)
void attn_main_kernel(const float* __restrict__ query,
                      const int*   __restrict__ bidx,
                      const float* __restrict__ bo,
                      float*       __restrict__ out) {
    extern __shared__ float sm[];
    float* Qs  = sm;                        // 32 x 65
    float* Ss  = Qs  + 32*QS_STRIDE;        // 32 x 129 (reused as T tile)
    float* Ps  = Ss  + 32*SS_STRIDE;        // 128 x 65
    float* bos = Ps  + RDIM*PS_STRIDE;      // 512
    int*   bt    = (int*)(bos + EMBED);     // 64
    int*   flags = bt + TN;                 // 8

    const int tid = threadIdx.x;
    const int tx  = tid & 15;               // r/e lane
    const int ty  = tid >> 4;               // token lane
    const int n0  = blockIdx.x * TN;

    if (tid < 8) flags[tid] = 0;
    bos[tid]       = bo[tid];
    bos[tid + 256] = bo[tid + 256];
    __syncthreads();
    if (tid < TN) { int b = bidx[n0 + tid]; bt[tid] = b; flags[b] = 1; }
    __syncthreads();

    for (int b = 0; b < NBATCH; b++) {
        if (!flags[b]) continue;
        const float* Sb = g_S + b*RDIM*EMBED;
        const float* Tb = g_T + b*RDIM*EMBED;

        // ---------------- Phase A: scores = Q @ S_b^T ----------------
        float acc[4][8];
        #pragma unroll
        for (int i = 0; i < 4; i++)
            #pragma unroll
            for (int j = 0; j < 8; j++) acc[i][j] = 0.f;

        for (int k0 = 0; k0 < EMBED; k0 += 32) {
            #pragma unroll
            for (int i = 0; i < 8; i++) {          // 64x32 / 256
                int idx = tid + i*256;
                int t = idx >> 5, kc = idx & 31;
                Qs[kc*QS_STRIDE + t] = query[(n0 + t)*EMBED + k0 + kc];
            }
            #pragma unroll
            for (int i = 0; i < 16; i++) {         // 128x32 / 256
                int idx = tid + i*256;
                int r = idx >> 5, kc = idx & 31;
                Ss[kc*SS_STRIDE + r] = Sb[r*EMBED + k0 + kc];
            }
            __syncthreads();
            #pragma unroll 8
            for (int kc = 0; kc < 32; kc++) {
                float qv[4], sv[8];
                #pragma unroll
                for (int i = 0; i < 4; i++) qv[i] = Qs[kc*QS_STRIDE + ty + 16*i];
                #pragma unroll
                for (int j = 0; j < 8; j++) sv[j] = Ss[kc*SS_STRIDE + tx + 16*j];
                #pragma unroll
                for (int i = 0; i < 4; i++)
                    #pragma unroll
                    for (int j = 0; j < 8; j++)
                        acc[i][j] += qv[i] * sv[j];
            }
            __syncthreads();
        }

        // ------- Phase B: softmax over l = tx (16 lanes), h = j -------
        #pragma unroll
        for (int i = 0; i < 4; i++) {
            #pragma unroll
            for (int j = 0; j < 8; j++) {
                float v = acc[i][j] + g_C[b*RDIM + 16*j + tx];
                float m = v;
                m = fmaxf(m, __shfl_xor_sync(0xFFFFFFFFu, m, 8));
                m = fmaxf(m, __shfl_xor_sync(0xFFFFFFFFu, m, 4));
                m = fmaxf(m, __shfl_xor_sync(0xFFFFFFFFu, m, 2));
                m = fmaxf(m, __shfl_xor_sync(0xFFFFFFFFu, m, 1));
                float e = __expf(v - m);
                float s = e;
                s += __shfl_xor_sync(0xFFFFFFFFu, s, 8);
                s += __shfl_xor_sync(0xFFFFFFFFu, s, 4);
                s += __shfl_xor_sync(0xFFFFFFFFu, s, 2);
                s += __shfl_xor_sync(0xFFFFFFFFu, s, 1);
                Ps[(16*j + tx)*PS_STRIDE + ty + 16*i] = e / s;
            }
        }

        // ---------------- Phase C: out = P @ T_b + bo ----------------
        for (int e0 = 0; e0 < EMBED; e0 += 128) {
            float oacc[4][8];
            #pragma unroll
            for (int i = 0; i < 4; i++)
                #pragma unroll
                for (int j = 0; j < 8; j++) oacc[i][j] = 0.f;

            for (int k0 = 0; k0 < RDIM; k0 += 32) {
                __syncthreads();                    // also orders Ps writes before first read
                #pragma unroll
                for (int i = 0; i < 16; i++) {      // 32x128 / 256
                    int idx = tid + i*256;
                    int ec = idx & 127, kcl = idx >> 7;
                    Ss[kcl*SS_STRIDE + ec] = Tb[(k0 + kcl)*EMBED + e0 + ec];
                }
                __syncthreads();
                #pragma unroll 8
                for (int kc = 0; kc < 32; kc++) {
                    float pv[4], tv[8];
                    #pragma unroll
                    for (int i = 0; i < 4; i++) pv[i] = Ps[(k0 + kc)*PS_STRIDE + ty + 16*i];
                    #pragma unroll
                    for (int j = 0; j < 8; j++) tv[j] = Ss[kc*SS_STRIDE + tx + 16*j];
                    #pragma unroll
                    for (int i = 0; i < 4; i++)
                        #pragma unroll
                        for (int j = 0; j < 8; j++)
                            oacc[i][j] += pv[i] * tv[j];
                }
            }
            #pragma unroll
            for (int i = 0; i < 4; i++) {
                int t = ty + 16*i;
                if (bt[t] == b) {
                    #pragma unroll
                    for (int j = 0; j < 8; j++) {
                        int e = e0 + tx + 16*j;
                        out[(n0 + t)*EMBED + e] = oacc[i][j] + bos[e];
                    }
                }
            }
        }
        __syncthreads();
    }
}

// ---------------------------------------------------------------------------
extern "C" void kernel_launch(void* const* d_in, const int* in_sizes, int n_in,
                              void* d_out, int out_size) {
    const float* query = (const float*)d_in[0];
    const float* key   = (const float*)d_in[1];
    const float* value = (const float*)d_in[2];
    const int*   bidx  = (const int*)  d_in[3];
    const int off = (n_in >= 13) ? 5 : 4;   // skip scalar batch_size if present
    const float* Wq = (const float*)d_in[off + 0];
    const float* bq = (const float*)d_in[off + 1];
    const float* Wk = (const float*)d_in[off + 2];
    const float* bk = (const float*)d_in[off + 3];
    const float* Wv = (const float*)d_in[off + 4];
    const float* bv = (const float*)d_in[off + 5];
    const float* Wo = (const float*)d_in[off + 6];
    const float* bo = (const float*)d_in[off + 7];
    float* out = (float*)d_out;

    const int smem_bytes = (32*QS_STRIDE + 32*SS_STRIDE + RDIM*PS_STRIDE + EMBED) * 4
                         + (TN + 8) * 4;
    cudaFuncSetAttribute(attn_main_kernel,
                         cudaFuncAttributeMaxDynamicSharedMemorySize, smem_bytes);

    proj_kv_kernel <<<32, 256>>>(key, value, Wk, bk, Wv, bv);
    build_st_kernel<<<512, 256>>>(Wq, bq, Wo);
    attn_main_kernel<<<N_TOKS / TN, 256, smem_bytes>>>(query, bidx, bo, out);
}

// round 5
// speedup vs baseline: 3.4392x; 1.8735x over previous
#include <cuda_runtime.h>
#include <cuda_bf16.h>

#define N_TOKS 32768
#define EMBED  512
#define NCLS   16
#define NBATCH 8
#define NHEAD  8
#define DHEAD  64
#define RDIM   128
#define SCALE  0.125f
#define TM     128

typedef unsigned int u32;

// precomputed bf16 hi/lo factor tables
__device__ __nv_bfloat16 g_Shi[NBATCH*RDIM*EMBED];   // [b][r][k]
__device__ __nv_bfloat16 g_Slo[NBATCH*RDIM*EMBED];
__device__ __nv_bfloat16 g_Thi[NBATCH*EMBED*RDIM];   // [b][e][r]
__device__ __nv_bfloat16 g_Tlo[NBATCH*EMBED*RDIM];
__device__ float g_C[NBATCH*RDIM];

// ---------------- warp-MMA helpers (family-portable PTX) ----------------
__device__ __forceinline__ u32 smem_u32(const void* p) {
    u32 a;
    asm("{ .reg .u64 t; cvta.to.shared.u64 t, %1; cvt.u32.u64 %0, t; }" : "=r"(a) : "l"(p));
    return a;
}
__device__ __forceinline__ void ldsm_x4(u32* r, u32 addr) {
    asm volatile("ldmatrix.sync.aligned.m8n8.x4.shared.b16 {%0,%1,%2,%3}, [%4];"
                 : "=r"(r[0]), "=r"(r[1]), "=r"(r[2]), "=r"(r[3]) : "r"(addr));
}
__device__ __forceinline__ void mma_bf16(float* c, const u32* a, u32 b0, u32 b1) {
    asm volatile("mma.sync.aligned.m16n8k16.row.col.f32.bf16.bf16.f32 "
                 "{%0,%1,%2,%3}, {%4,%5,%6,%7}, {%8,%9}, {%0,%1,%2,%3};"
                 : "+f"(c[0]), "+f"(c[1]), "+f"(c[2]), "+f"(c[3])
                 : "r"(a[0]), "r"(a[1]), "r"(a[2]), "r"(a[3]), "r"(b0), "r"(b1));
}
__device__ __forceinline__ u32 pack_hi_lo(float x, float y, u32& lo) {
    __nv_bfloat16 hx = __float2bfloat16_rn(x), hy = __float2bfloat16_rn(y);
    __nv_bfloat16 lx = __float2bfloat16_rn(x - __bfloat162float(hx));
    __nv_bfloat16 ly = __float2bfloat16_rn(y - __bfloat162float(hy));
    lo = (u32)__bfloat16_as_ushort(lx) | ((u32)__bfloat16_as_ushort(ly) << 16);
    return (u32)__bfloat16_as_ushort(hx) | ((u32)__bfloat16_as_ushort(hy) << 16);
}

// ---------------------------------------------------------------------------
// Precompute: per (b,h): KP/VP slice in smem, fold Wq->S(+C) or Wo->T (bf16 hi/lo)
// grid = 128 blocks: isT = x&1, h = (x>>1)&7, b = (x>>4)&7.
// ---------------------------------------------------------------------------
__global__ __launch_bounds__(256)
void precompute_kernel(const float* __restrict__ key, const float* __restrict__ value,
                       const float* __restrict__ Wq, const float* __restrict__ bq,
                       const float* __restrict__ Wk, const float* __restrict__ bk,
                       const float* __restrict__ Wv, const float* __restrict__ bv,
                       const float* __restrict__ Wo) {
    __shared__ float Ks[16][65];
    __shared__ float KPs[16][65];
    __shared__ float Ws[64][129];

    const int x = blockIdx.x;
    const int isT = x & 1;
    const int h   = (x >> 1) & 7;
    const int b   = (x >> 4) & 7;
    const int tid = threadIdx.x;

    const float* src = isT ? value : key;
    const float* W1  = isT ? Wv : Wk;
    const float* b1  = isT ? bv : bk;

    // phase 1: KP[l][d] = sum_e src[l,b,e]*W1[h*64+d,e] + b1[h*64+d]
    const int d   = tid & 63;
    const int lg4 = tid >> 6;
    float acc[4] = {0.f, 0.f, 0.f, 0.f};
    for (int e0 = 0; e0 < EMBED; e0 += 64) {
        #pragma unroll
        for (int i = 0; i < 4; i++) {
            int idx = tid + i*256; int l = idx >> 6, e = idx & 63;
            Ks[l][e] = src[(l*NBATCH + b)*EMBED + e0 + e];
        }
        #pragma unroll
        for (int i = 0; i < 16; i++) {
            int idx = tid + i*256; int dd = idx >> 6, e = idx & 63;
            Ws[dd][e] = W1[(h*DHEAD + dd)*EMBED + e0 + e];
        }
        __syncthreads();
        #pragma unroll 8
        for (int e = 0; e < 64; e++) {
            float wv = Ws[d][e];
            #pragma unroll
            for (int i = 0; i < 4; i++) acc[i] += Ks[lg4*4 + i][e] * wv;
        }
        __syncthreads();
    }
    {
        float bias = b1[h*DHEAD + d];
        #pragma unroll
        for (int i = 0; i < 4; i++) KPs[lg4*4 + i][d] = acc[i] + bias;
    }
    __syncthreads();

    const int fc = tid & 127, lg = tid >> 7;
    if (!isT) {
        if (tid < 16) {
            float c = 0.f;
            #pragma unroll 8
            for (int dd = 0; dd < DHEAD; dd++) c += KPs[tid][dd] * bq[h*DHEAD + dd];
            g_C[b*RDIM + h*NCLS + tid] = c * SCALE;
        }
        for (int f0 = 0; f0 < EMBED; f0 += 128) {
            #pragma unroll
            for (int i = 0; i < 32; i++) {
                int idx = tid + i*256; int dd = idx >> 7, f = idx & 127;
                Ws[dd][f] = Wq[(h*DHEAD + dd)*EMBED + f0 + f];
            }
            __syncthreads();
            float a2[8] = {0,0,0,0,0,0,0,0};
            #pragma unroll 8
            for (int dd = 0; dd < DHEAD; dd++) {
                float wv = Ws[dd][fc];
                #pragma unroll
                for (int i = 0; i < 8; i++) a2[i] += KPs[lg*8 + i][dd] * wv;
            }
            #pragma unroll
            for (int i = 0; i < 8; i++) {
                int r = h*NCLS + lg*8 + i;
                float v = a2[i] * SCALE;
                __nv_bfloat16 hi = __float2bfloat16_rn(v);
                float lo = v - __bfloat162float(hi);
                g_Shi[(b*RDIM + r)*EMBED + f0 + fc] = hi;
                g_Slo[(b*RDIM + r)*EMBED + f0 + fc] = __float2bfloat16_rn(lo);
            }
            __syncthreads();
        }
    } else {
        for (int e0 = 0; e0 < EMBED; e0 += 128) {
            #pragma unroll
            for (int i = 0; i < 32; i++) {
                int idx = tid + i*256; int e = idx >> 6, dd = idx & 63;
                Ws[dd][e] = Wo[(e0 + e)*EMBED + h*DHEAD + dd];
            }
            __syncthreads();
            float a2[8] = {0,0,0,0,0,0,0,0};
            #pragma unroll 8
            for (int dd = 0; dd < DHEAD; dd++) {
                float wv = Ws[dd][fc];
                #pragma unroll
                for (int i = 0; i < 8; i++) a2[i] += KPs[lg*8 + i][dd] * wv;
            }
            u32 hw[4], lw[4];
            #pragma unroll
            for (int i = 0; i < 4; i++)
                hw[i] = pack_hi_lo(a2[2*i], a2[2*i+1], lw[i]);
            long long ofs = ((long long)(b*EMBED + e0 + fc))*RDIM + h*NCLS + lg*8;
            *(uint4*)&g_Thi[ofs] = make_uint4(hw[0], hw[1], hw[2], hw[3]);
            *(uint4*)&g_Tlo[ofs] = make_uint4(lw[0], lw[1], lw[2], lw[3]);
            __syncthreads();
        }
    }
}

// ---------------------------------------------------------------------------
// Main attention kernel: 128 tokens/block, 256 threads (8 warps), mma.sync bf16
// ---------------------------------------------------------------------------
// smem layout (bytes)
#define SM_P_HI  0                      // P hi tile: 128 rows x 256B, xor-swizzled
#define SM_P_LO  32768
#define SM_QHI   65536                  // phase A: 128 rows x 80B (32k, pad to 40)
#define SM_QLO   (65536 + 10240)
#define SM_SHI   (65536 + 20480)
#define SM_SLO   (65536 + 30720)
#define SM_THI   65536                  // phase C: 32 rows x 272B (128r, pad 136)
#define SM_TLO   (65536 + 8704)
#define SM_BO    106496                 // 512 f32
#define SM_CS    108544                 // 128 f32
#define SM_BT    109056                 // 128 int
#define SMEM_ATTN 109568

__global__ __launch_bounds__(256, 2)
void attn_mma_kernel(const float* __restrict__ query,
                     const int*   __restrict__ bidx,
                     const float* __restrict__ bo,
                     float*       __restrict__ out) {
    extern __shared__ char sm[];
    const u32 sb = smem_u32(sm);

    const int tid  = threadIdx.x;
    const int lane = tid & 31, wid = tid >> 5;
    const int n0   = blockIdx.x * TM;
    const int m0   = wid * 16;
    const int qr   = lane >> 2;        // quad row (0..7)
    const int qc   = lane & 3;         // quad col (0..3)

    float* bos = (float*)(sm + SM_BO);
    int*   bt  = (int*)(sm + SM_BT);
    bos[tid]       = bo[tid];
    bos[tid + 256] = bo[tid + 256];
    if (tid < TM) bt[tid] = bidx[n0 + tid];
    __syncthreads();
    const int b_lo = bt[0], b_hi = bt[TM - 1];

    // lane-invariant ldmatrix address components
    const u32 arow    = m0 + (lane & 15);
    const u32 akoff   = (lane >> 4) << 3;           // +0 / +8 in k
    const u32 browoff = ((lane >> 4) << 3) + (lane & 7);
    const u32 bkoff   = ((lane >> 3) & 1) << 3;

    for (int b = b_lo; b <= b_hi; b++) {
        if (tid < 128) ((float*)(sm + SM_CS))[tid] = g_C[b*RDIM + tid];

        // ================= Phase A: scores = Q @ S_b^T (K=512) =================
        float acc[16][4];
        #pragma unroll
        for (int i = 0; i < 16; i++)
            #pragma unroll
            for (int j = 0; j < 4; j++) acc[i][j] = 0.f;

        for (int kc = 0; kc < 16; kc++) {
            const int k0 = kc * 32;
            __syncthreads();
            // stage Q chunk (f32 -> bf16 hi/lo), 128 rows x 32 k
            #pragma unroll
            for (int i = 0; i < 4; i++) {
                int idx = tid + i*256;
                int row = idx >> 3, c4 = idx & 7;
                float4 q = *(const float4*)(query + (long long)(n0 + row)*EMBED + k0 + c4*4);
                uint2 hv, lv;
                hv.x = pack_hi_lo(q.x, q.y, lv.x);
                hv.y = pack_hi_lo(q.z, q.w, lv.y);
                *(uint2*)(sm + SM_QHI + row*80 + c4*8) = hv;
                *(uint2*)(sm + SM_QLO + row*80 + c4*8) = lv;
            }
            // stage S chunk (bf16 copy), 128 rows x 32 k, hi+lo
            #pragma unroll
            for (int i = 0; i < 4; i++) {
                int idx = tid + i*256;
                int half = idx >> 9, j = idx & 511;
                int row = j >> 2, c = j & 3;
                const __nv_bfloat16* src = half ? g_Slo : g_Shi;
                uint4 v = *(const uint4*)(src + (long long)(b*RDIM + row)*EMBED + k0 + c*8);
                *(uint4*)(sm + (half ? SM_SLO : SM_SHI) + row*80 + c*16) = v;
            }
            __syncthreads();
            #pragma unroll
            for (int kk2 = 0; kk2 < 2; kk2++) {
                const u32 kk = kk2 * 16;
                u32 ah[4], al[4];
                ldsm_x4(ah, sb + SM_QHI + arow*80 + (kk + akoff)*2);
                ldsm_x4(al, sb + SM_QLO + arow*80 + (kk + akoff)*2);
                #pragma unroll
                for (int nt2 = 0; nt2 < 8; nt2++) {
                    u32 bh[4], bl[4];
                    u32 brow = nt2*16 + browoff;
                    ldsm_x4(bh, sb + SM_SHI + brow*80 + (kk + bkoff)*2);
                    ldsm_x4(bl, sb + SM_SLO + brow*80 + (kk + bkoff)*2);
                    mma_bf16(acc[2*nt2],   ah, bh[0], bh[1]);
                    mma_bf16(acc[2*nt2+1], ah, bh[2], bh[3]);
                    mma_bf16(acc[2*nt2],   ah, bl[0], bl[1]);
                    mma_bf16(acc[2*nt2+1], ah, bl[2], bl[3]);
                    mma_bf16(acc[2*nt2],   al, bh[0], bh[1]);
                    mma_bf16(acc[2*nt2+1], al, bh[2], bh[3]);
                }
            }
        }

        // ================= softmax (per head, quad-reduce) + P -> smem =========
        {
            const float* Cs = (const float*)(sm + SM_CS);
            #pragma unroll
            for (int h = 0; h < 8; h++) {
                float c0 = Cs[h*16 + 2*qc],     c1 = Cs[h*16 + 2*qc + 1];
                float c2 = Cs[h*16 + 8 + 2*qc], c3 = Cs[h*16 + 8 + 2*qc + 1];
                #pragma unroll
                for (int t = 0; t < 2; t++) {
                    float v0 = acc[2*h][2*t]     + c0;
                    float v1 = acc[2*h][2*t+1]   + c1;
                    float v2 = acc[2*h+1][2*t]   + c2;
                    float v3 = acc[2*h+1][2*t+1] + c3;
                    float mx = fmaxf(fmaxf(v0, v1), fmaxf(v2, v3));
                    mx = fmaxf(mx, __shfl_xor_sync(0xFFFFFFFFu, mx, 1));
                    mx = fmaxf(mx, __shfl_xor_sync(0xFFFFFFFFu, mx, 2));
                    float e0 = __expf(v0 - mx), e1 = __expf(v1 - mx);
                    float e2 = __expf(v2 - mx), e3 = __expf(v3 - mx);
                    float s = e0 + e1 + e2 + e3;
                    s += __shfl_xor_sync(0xFFFFFFFFu, s, 1);
                    s += __shfl_xor_sync(0xFFFFFFFFu, s, 2);
                    float inv = 1.f / s;
                    u32 lo0, lo1;
                    u32 hi0 = pack_hi_lo(e0*inv, e1*inv, lo0);
                    u32 hi1 = pack_hi_lo(e2*inv, e3*inv, lo1);
                    int mrow = m0 + qr + t*8;
                    u32 sw = (u32)(mrow & 7) << 4;
                    u32 cb0 = (u32)(h*32 + 4*qc) ^ sw;
                    u32 cb1 = (u32)(h*32 + 16 + 4*qc) ^ sw;
                    *(u32*)(sm + SM_P_HI + mrow*256 + cb0) = hi0;
                    *(u32*)(sm + SM_P_HI + mrow*256 + cb1) = hi1;
                    *(u32*)(sm + SM_P_LO + mrow*256 + cb0) = lo0;
                    *(u32*)(sm + SM_P_LO + mrow*256 + cb1) = lo1;
                }
            }
        }

        // ================= Phase C: out = P @ T_b + bo =========================
        for (int ec = 0; ec < 16; ec++) {
            const int e0 = ec * 32;
            __syncthreads();
            // stage T chunk: 32 e rows x 128 r, hi+lo
            #pragma unroll
            for (int i = 0; i < 4; i++) {
                int idx = tid + i*256;
                int half = idx >> 9, j = idx & 511;
                int row = j >> 4, c = j & 15;
                const __nv_bfloat16* src = half ? g_Tlo : g_Thi;
                uint4 v = *(const uint4*)(src + (long long)(b*EMBED + e0 + row)*RDIM + c*8);
                *(uint4*)(sm + (half ? SM_TLO : SM_THI) + row*272 + c*16) = v;
            }
            __syncthreads();

            float oc[4][4];
            #pragma unroll
            for (int i = 0; i < 4; i++)
                #pragma unroll
                for (int j = 0; j < 4; j++) oc[i][j] = 0.f;

            #pragma unroll
            for (int kk8 = 0; kk8 < 8; kk8++) {
                const u32 kk = kk8 * 16;
                u32 akb = (kk + akoff) * 2;
                u32 asw = akb ^ ((u32)(arow & 7) << 4);
                u32 ah[4], al[4];
                ldsm_x4(ah, sb + SM_P_HI + arow*256 + asw);
                ldsm_x4(al, sb + SM_P_LO + arow*256 + asw);
                #pragma unroll
                for (int ne = 0; ne < 2; ne++) {
                    u32 bh[4], bl[4];
                    u32 brow = ne*16 + browoff;
                    ldsm_x4(bh, sb + SM_THI + brow*272 + (kk + bkoff)*2);
                    ldsm_x4(bl, sb + SM_TLO + brow*272 + (kk + bkoff)*2);
                    mma_bf16(oc[2*ne],   ah, bh[0], bh[1]);
                    mma_bf16(oc[2*ne+1], ah, bh[2], bh[3]);
                    mma_bf16(oc[2*ne],   ah, bl[0], bl[1]);
                    mma_bf16(oc[2*ne+1], ah, bl[2], bl[3]);
                    mma_bf16(oc[2*ne],   al, bh[0], bh[1]);
                    mma_bf16(oc[2*ne+1], al, bh[2], bh[3]);
                }
            }
            // epilogue: masked write + bias
            #pragma unroll
            for (int t = 0; t < 2; t++) {
                int mrow = m0 + qr + t*8;
                if (bt[mrow] == b) {
                    #pragma unroll
                    for (int nt = 0; nt < 4; nt++) {
                        int e = e0 + nt*8 + 2*qc;
                        float2 w;
                        w.x = oc[nt][2*t]   + bos[e];
                        w.y = oc[nt][2*t+1] + bos[e+1];
                        *(float2*)(out + (long long)(n0 + mrow)*EMBED + e) = w;
                    }
                }
            }
        }
        __syncthreads();
    }
}

// ---------------------------------------------------------------------------
extern "C" void kernel_launch(void* const* d_in, const int* in_sizes, int n_in,
                              void* d_out, int out_size) {
    const float* query = (const float*)d_in[0];
    const float* key   = (const float*)d_in[1];
    const float* value = (const float*)d_in[2];
    const int*   bidx  = (const int*)  d_in[3];
    const int off = (n_in >= 13) ? 5 : 4;   // skip scalar batch_size if present
    const float* Wq = (const float*)d_in[off + 0];
    const float* bq = (const float*)d_in[off + 1];
    const float* Wk = (const float*)d_in[off + 2];
    const float* bk = (const float*)d_in[off + 3];
    const float* Wv = (const float*)d_in[off + 4];
    const float* bv = (const float*)d_in[off + 5];
    const float* Wo = (const float*)d_in[off + 6];
    const float* bo = (const float*)d_in[off + 7];
    float* out = (float*)d_out;

    cudaFuncSetAttribute(attn_mma_kernel,
                         cudaFuncAttributeMaxDynamicSharedMemorySize, SMEM_ATTN);

    precompute_kernel<<<128, 256>>>(key, value, Wq, bq, Wk, bk, Wv, bv, Wo);
    attn_mma_kernel<<<N_TOKS / TM, 256, SMEM_ATTN>>>(query, bidx, bo, out);
}